// round 11
// baseline (speedup 1.0000x reference)
#include <cuda_runtime.h>
#include <cuda_fp16.h>
#include <cstdint>

// ---------------- problem constants ----------------
#define M_TOTAL 8192          // data rows (output rows)
#define N_TOTAL 4096          // W rows (output cols)
#define K_TOTAL 4096
#define KT_CNT  128           // K / 32

// ---------------- GEMM tiling: block = 128 n (W rows) x 128 m (data rows) ----------------
#define STAGES 4
#define A_ST_BYTES 4096       // 128 W-rows x 16 compressed halfs
#define B_ST_BYTES 8192       // 128 data-rows x 32 halfs
#define E_ST_BYTES 512        // 128 u32 metadata
#define OFF_B (STAGES * A_ST_BYTES)
#define OFF_E (OFF_B + STAGES * B_ST_BYTES)
#define SMEM_BYTES (OFF_E + STAGES * E_ST_BYTES)   // 51200 -> 2 CTAs/SM
// epilogue staging: 128 x 69 floats = 35328 B (reuses the same smem)

#define RES_CAP (1u << 18)

// ---------------- device scratch ----------------
__device__ __half   g_Bv [(size_t)M_TOTAL * K_TOTAL];        // data fp16, frag-permuted
__device__ __half   g_dT [(size_t)K_TOTAL * M_TOTAL];        // data^T fp16
__device__ __half   g_Ac [(size_t)N_TOTAL * (K_TOTAL / 2)];  // compressed W (2:4)
__device__ uint32_t g_meta[(size_t)N_TOTAL * KT_CNT];
__device__ uint32_t g_E  [(size_t)(N_TOTAL / 128) * KT_CNT * 128];
__device__ uint32_t g_rn [RES_CAP];   // packed (n<<12)|k
__device__ float    g_rv [RES_CAP];
__device__ uint32_t g_srn[RES_CAP];   // sorted by n
__device__ float    g_srv[RES_CAP];
__device__ uint32_t g_rcnt;
__device__ uint32_t g_bins[N_TOTAL];
__device__ uint32_t g_start[N_TOTAL + 1];
__device__ uint32_t g_cursor[N_TOTAL];

// ---------------- reset ----------------
__global__ void rs_zero() {
    int i = blockIdx.x * blockDim.x + threadIdx.x;
    if (i < N_TOTAL) g_bins[i] = 0;
    if (i == 0) g_rcnt = 0;
}

// ---------------- prep: data -> g_Bv (permuted fp16) + g_dT (fp16 transpose) ----------------
// 32m x 32k tile per block; each tile is exactly one 32-k permutation block.
__global__ __launch_bounds__(256)
void prep_data2(const float* __restrict__ data) {
    __shared__ float ts[32][33];
    const int tx = threadIdx.x, ty = threadIdx.y;
    const int k0 = blockIdx.x * 32, m0 = blockIdx.y * 32;
    #pragma unroll
    for (int i = 0; i < 4; i++)
        ts[ty + i * 8][tx] = data[(size_t)(m0 + ty + i * 8) * K_TOTAL + k0 + tx];
    __syncthreads();
    // dT: coalesced along m (transposed read from smem, padded)
    #pragma unroll
    for (int i = 0; i < 4; i++)
        g_dT[(size_t)(k0 + ty + i * 8) * M_TOTAL + m0 + tx] =
            __float2half(ts[tx][ty + i * 8]);
    // Bv: row m, permuted position p=tx -> source k
    {
        const int t = tx >> 3, rem = tx & 7, hh = rem >> 1, d = rem & 1;
        const int k = 8 * hh + 2 * t + d;
        #pragma unroll
        for (int i = 0; i < 4; i++)
            g_Bv[(size_t)(m0 + ty + i * 8) * K_TOTAL + k0 + tx] =
                __float2half(ts[ty + i * 8][k]);
    }
}

// ---------------- prep: W*mask -> 2:4 compressed + meta + residual ----------------
__global__ __launch_bounds__(128)
void prep_w(const float* __restrict__ w, const float* __restrict__ msk) {
    const int n  = blockIdx.x;
    const int kt = threadIdx.x;
    const float4* wp = reinterpret_cast<const float4*>(w   + (size_t)n * K_TOTAL + kt * 32);
    const float4* mp = reinterpret_cast<const float4*>(msk + (size_t)n * K_TOTAL + kt * 32);
    alignas(16) __half hh[16];
    uint32_t meta = 0;
    #pragma unroll
    for (int j = 0; j < 8; j++) {
        float4 wv = __ldg(wp + j);
        float4 mv4 = __ldg(mp + j);
        float pv[4] = {wv.x * mv4.x, wv.y * mv4.y, wv.z * mv4.z, wv.w * mv4.w};
        float mm[4] = {mv4.x, mv4.y, mv4.z, mv4.w};
        float v[4];
        int idx[4], cnt = 0;
        #pragma unroll
        for (int s = 0; s < 4; s++)
            if (mm[s] != 0.0f) { v[cnt] = pv[s]; idx[cnt] = s; cnt++; }
        int i0, i1; float v0, v1;
        if (cnt == 0)      { i0 = 0; i1 = 1; v0 = 0.f; v1 = 0.f; }
        else if (cnt == 1) {
            int p = idx[0];
            if (p == 3) { i0 = 2; i1 = 3; v0 = 0.f; v1 = v[0]; }
            else        { i0 = p; i1 = p + 1; v0 = v[0]; v1 = 0.f; }
        } else {
            i0 = idx[0]; i1 = idx[1]; v0 = v[0]; v1 = v[1];
            for (int s = 2; s < cnt; s++) {
                uint32_t pos = atomicAdd(&g_rcnt, 1u);
                if (pos < RES_CAP) {
                    g_rn[pos] = ((uint32_t)n << 12) | (uint32_t)(kt * 32 + j * 4 + idx[s]);
                    g_rv[pos] = v[s];
                }
            }
        }
        meta |= (uint32_t)(i0 | (i1 << 2)) << (4 * j);
        int c0 = 2 * j, c1 = 2 * j + 1;
        hh[((c0 >> 1) & 3) * 4 + (c0 >> 3) * 2 + (c0 & 1)] = __float2half(v0);
        hh[((c1 >> 1) & 3) * 4 + (c1 >> 3) * 2 + (c1 & 1)] = __float2half(v1);
    }
    uint4* dst = reinterpret_cast<uint4*>(g_Ac + (size_t)n * 2048 + kt * 16);
    dst[0] = reinterpret_cast<uint4*>(hh)[0];
    dst[1] = reinterpret_cast<uint4*>(hh)[1];
    g_meta[(size_t)n * KT_CNT + kt] = meta;
}

// ---------------- prep: assemble E registers ----------------
__global__ __launch_bounds__(256)
void prep_E() {
    int i = blockIdx.x * blockDim.x + threadIdx.x;       // 524288
    int nb = i >> 14, rem = i & 16383;
    int kt = rem >> 7, q = rem & 127;
    int p = q >> 1, h = q & 1;
    int r = (p >> 3) * 16 + (p & 7);
    int n0 = nb * 128 + r;
    uint32_t m0 = g_meta[(size_t)n0 * KT_CNT + kt];
    uint32_t m1 = g_meta[(size_t)(n0 + 8) * KT_CNT + kt];
    g_E[i] = ((m0 >> (16 * h)) & 0xFFFFu) | (((m1 >> (16 * h)) & 0xFFFFu) << 16);
}

// ---------------- residual sort by n ----------------
__global__ void rs_count() {
    uint32_t i = blockIdx.x * blockDim.x + threadIdx.x;
    if (i < g_rcnt && i < RES_CAP) atomicAdd(&g_bins[g_rn[i] >> 12], 1u);
}
__global__ __launch_bounds__(1024)
void rs_prefix() {
    __shared__ uint32_t ts[1024];
    int t = threadIdx.x;
    uint32_t loc[4], sum = 0;
    #pragma unroll
    for (int u = 0; u < 4; u++) { loc[u] = g_bins[t * 4 + u]; sum += loc[u]; }
    ts[t] = sum; __syncthreads();
    for (int off = 1; off < 1024; off <<= 1) {
        uint32_t v = (t >= off) ? ts[t - off] : 0; __syncthreads();
        ts[t] += v; __syncthreads();
    }
    uint32_t run = ts[t] - sum;
    #pragma unroll
    for (int u = 0; u < 4; u++) {
        g_start[t * 4 + u] = run; g_cursor[t * 4 + u] = run; run += loc[u];
    }
    if (t == 1023) g_start[N_TOTAL] = run;
}
__global__ void rs_scatter() {
    uint32_t i = blockIdx.x * blockDim.x + threadIdx.x;
    if (i < g_rcnt && i < RES_CAP) {
        uint32_t nk = g_rn[i];
        uint32_t pos = atomicAdd(&g_cursor[nk >> 12], 1u);
        g_srn[pos] = nk; g_srv[pos] = g_rv[i];
    }
}

// ---------------- sparse GEMM with fused epilogue ----------------
__device__ __forceinline__ void cp_async16(void* dst, const void* src) {
    unsigned sdst = (unsigned)__cvta_generic_to_shared(dst);
    asm volatile("cp.async.cg.shared.global [%0], [%1], 16;" :: "r"(sdst), "l"(src));
}

__device__ __forceinline__ void mma_sp(float* c,
                                       unsigned a0, unsigned a1, unsigned a2, unsigned a3,
                                       const uint4& b, unsigned e) {
    asm volatile(
        "mma.sp::ordered_metadata.sync.aligned.m16n8k32.row.col.f32.f16.f16.f32 "
        "{%0,%1,%2,%3}, {%4,%5,%6,%7}, {%8,%9,%10,%11}, {%0,%1,%2,%3}, %12, 0x0;"
        : "+f"(c[0]), "+f"(c[1]), "+f"(c[2]), "+f"(c[3])
        : "r"(a0), "r"(a1), "r"(a2), "r"(a3),
          "r"(b.x), "r"(b.y), "r"(b.z), "r"(b.w), "r"(e));
}

#define ST_STRIDE 69   // gcd(69,32)=1 -> column sweeps conflict-free

__global__ __launch_bounds__(256, 2)
void gemm_sp_kernel(float* __restrict__ out, const float* __restrict__ bias) {
    extern __shared__ char smem[];
    char* As = smem;                 // [STAGES][128][32B]
    char* Bs = smem + OFF_B;         // [STAGES][128][64B]
    uint32_t* Es = reinterpret_cast<uint32_t*>(smem + OFF_E);

    const int tid  = threadIdx.x;
    const int wid  = tid >> 5;
    const int lane = tid & 31;
    const int g    = lane >> 2;
    const int t4   = lane & 3;

    const int wn = (wid & 1) * 64;       // W-row (output col) offset
    const int wm = (wid >> 1) * 32;      // data-row (output row) offset

    const int Nb = blockIdx.y * 128;
    const int Mb = blockIdx.x * 128;

    float acc[4][4][4];
    #pragma unroll
    for (int i = 0; i < 4; i++)
        #pragma unroll
        for (int j = 0; j < 4; j++)
            #pragma unroll
            for (int r = 0; r < 4; r++) acc[i][j][r] = 0.0f;

    auto load_stage = [&](int kt) {
        const int buf = kt & (STAGES - 1);
        {   // A: 256 x 16B
            int row = tid >> 1, hb = tid & 1;
            cp_async16(As + buf * A_ST_BYTES + row * 32 + hb * 16,
                       g_Ac + (size_t)(Nb + row) * 2048 + kt * 16 + hb * 8);
        }
        #pragma unroll
        for (int it = 0; it < 2; it++) {   // B: 512 x 16B
            int idx = tid + it * 256;
            int row = idx >> 2, ch = idx & 3;
            cp_async16(Bs + buf * B_ST_BYTES + row * 64 + ch * 16,
                       g_Bv + (size_t)(Mb + row) * K_TOTAL + kt * 32 + ch * 8);
        }
        if (tid < 32)
            cp_async16(reinterpret_cast<char*>(Es) + buf * E_ST_BYTES + tid * 16,
                       g_E + ((size_t)blockIdx.y * KT_CNT + kt) * 128 + tid * 4);
        asm volatile("cp.async.commit_group;");
    };

    load_stage(0);
    load_stage(1);
    load_stage(2);

    for (int kt = 0; kt < KT_CNT; ++kt) {
        asm volatile("cp.async.wait_group 2;");
        __syncthreads();
        if (kt + 3 < KT_CNT) load_stage(kt + 3);
        else asm volatile("cp.async.commit_group;");

        const int buf = kt & (STAGES - 1);
        const char* Ab = As + buf * A_ST_BYTES;
        const char* Bb = Bs + buf * B_ST_BYTES;
        const uint32_t* Eb = Es + buf * 128;

        uint4 bQ[4];
        #pragma unroll
        for (int j = 0; j < 4; j++)
            bQ[j] = *reinterpret_cast<const uint4*>(Bb + (wm + j * 8 + g) * 64 + t4 * 16);

        #pragma unroll
        for (int i = 0; i < 4; i++) {
            int r = wn + i * 16 + g;
            uint2 ra = *reinterpret_cast<const uint2*>(Ab + r * 32 + t4 * 8);
            uint2 rb = *reinterpret_cast<const uint2*>(Ab + (r + 8) * 32 + t4 * 8);
            unsigned e = Eb[((wn >> 4) + i) * 16 + g * 2 + (t4 & 1)];
            #pragma unroll
            for (int j = 0; j < 4; j++)
                mma_sp(acc[i][j], ra.x, rb.x, ra.y, rb.y, bQ[j], e);
        }
    }

    // -------- fused epilogue: transpose + residual + bias, per 64-n half --------
    float* st = reinterpret_cast<float*>(smem);   // [128 m][ST_STRIDE]
    #pragma unroll
    for (int h = 0; h < 2; h++) {
        __syncthreads();   // smem free (mainloop done / previous half stored)
        if ((wid & 1) == h) {
            #pragma unroll
            for (int i = 0; i < 4; i++) {
                int ncol = i * 16 + g;
                #pragma unroll
                for (int j = 0; j < 4; j++) {
                    int m0 = wm + j * 8 + 2 * t4;
                    st[m0 * ST_STRIDE + ncol]           = acc[i][j][0];
                    st[(m0 + 1) * ST_STRIDE + ncol]     = acc[i][j][1];
                    st[m0 * ST_STRIDE + ncol + 8]       = acc[i][j][2];
                    st[(m0 + 1) * ST_STRIDE + ncol + 8] = acc[i][j][3];
                }
            }
        }
        __syncthreads();

        // residual: thread owns (m = tid&127, cols c = 2*ci + tid>>7) -> race-free
        const int nbase = Nb + h * 64;
        const int m_l = tid & 127;
        const int grp = tid >> 7;
        #pragma unroll 4
        for (int ci = 0; ci < 32; ci++) {
            int c = 2 * ci + grp;
            uint32_t s0 = __ldg(&g_start[nbase + c]);
            uint32_t e0 = __ldg(&g_start[nbase + c + 1]);
            if (s0 != e0) {
                float val = st[m_l * ST_STRIDE + c];
                for (uint32_t q = s0; q < e0; q++) {
                    int k = (int)(__ldg(&g_srn[q]) & 0xFFFu);
                    val += __ldg(&g_srv[q]) *
                           __half2float(__ldg(&g_dT[(size_t)k * M_TOTAL + Mb + m_l]));
                }
                st[m_l * ST_STRIDE + c] = val;
            }
        }
        __syncthreads();

        // store: 128 rows x 64 cols, coalesced float4 along n
        #pragma unroll
        for (int it = 0; it < 8; it++) {
            int idx = tid + it * 256;
            int m = idx >> 4;
            int c4 = (idx & 15) * 4;
            const float* p = st + m * ST_STRIDE + c4;
            float4 v;
            v.x = p[0] + __ldg(bias + nbase + c4);
            v.y = p[1] + __ldg(bias + nbase + c4 + 1);
            v.z = p[2] + __ldg(bias + nbase + c4 + 2);
            v.w = p[3] + __ldg(bias + nbase + c4 + 3);
            *reinterpret_cast<float4*>(out + (size_t)(Mb + m) * N_TOTAL + nbase + c4) = v;
        }
    }
}

// ---------------- host ----------------
extern "C" void kernel_launch(void* const* d_in, const int* in_sizes, int n_in,
                              void* d_out, int out_size) {
    const float* data   = (const float*)d_in[0];
    const float* weight = (const float*)d_in[1];
    const float* w_mask = (const float*)d_in[2];
    const float* bias_p = (const float*)d_in[3];
    float* out = (float*)d_out;

    rs_zero<<<(N_TOTAL + 255) / 256, 256>>>();
    prep_data2<<<dim3(K_TOTAL / 32, M_TOTAL / 32), dim3(32, 8)>>>(data);
    prep_w<<<N_TOTAL, 128>>>(weight, w_mask);
    prep_E<<<(N_TOTAL / 128) * KT_CNT * 128 / 256, 256>>>();
    rs_count<<<RES_CAP / 256, 256>>>();
    rs_prefix<<<1, 1024>>>();
    rs_scatter<<<RES_CAP / 256, 256>>>();

    cudaFuncSetAttribute(gemm_sp_kernel,
                         cudaFuncAttributeMaxDynamicSharedMemorySize, SMEM_BYTES);
    gemm_sp_kernel<<<dim3(M_TOTAL / 128, N_TOTAL / 128), 256, SMEM_BYTES>>>(out, bias_p);
}

// round 12
// speedup vs baseline: 1.4094x; 1.4094x over previous
#include <cuda_runtime.h>
#include <cuda_fp16.h>
#include <cstdint>

// ---------------- problem constants ----------------
#define M_TOTAL 8192          // data rows (output rows)
#define N_TOTAL 4096          // W rows (output cols)
#define K_TOTAL 4096
#define KT_CNT  128           // K / 32

// ---------------- GEMM tiling: block = 128 n (W rows) x 128 m (data rows) ----------------
#define STAGES 4
#define A_ST_BYTES 4096       // 128 W-rows x 16 compressed halfs
#define B_ST_BYTES 8192       // 128 data-rows x 32 halfs
#define E_ST_BYTES 512        // 128 u32 metadata
#define OFF_B (STAGES * A_ST_BYTES)
#define OFF_E (OFF_B + STAGES * B_ST_BYTES)
#define SMEM_BYTES (OFF_E + STAGES * E_ST_BYTES)   // 51200 -> 2 CTAs/SM

#define RES_CAP (1u << 18)

// ---------------- device scratch ----------------
__device__ __half   g_Bv [(size_t)M_TOTAL * K_TOTAL];        // data fp16, frag-permuted
__device__ __half   g_dT [(size_t)K_TOTAL * M_TOTAL];        // data^T fp16
__device__ __half   g_Ac [(size_t)N_TOTAL * (K_TOTAL / 2)];  // compressed W (2:4)
__device__ uint32_t g_meta[(size_t)N_TOTAL * KT_CNT];
__device__ uint32_t g_E  [(size_t)(N_TOTAL / 128) * KT_CNT * 128];
__device__ float    g_outT[(size_t)N_TOTAL * M_TOTAL];       // transposed output staging
__device__ uint32_t g_rn [RES_CAP];   // packed (n<<12)|k
__device__ float    g_rv [RES_CAP];
__device__ uint32_t g_srn[RES_CAP];   // sorted by n
__device__ float    g_srv[RES_CAP];
__device__ uint32_t g_rcnt;
__device__ uint32_t g_bins[N_TOTAL];
__device__ uint32_t g_start[N_TOTAL + 1];
__device__ uint32_t g_cursor[N_TOTAL];

// ---------------- reset ----------------
__global__ void rs_zero() {
    int i = blockIdx.x * blockDim.x + threadIdx.x;
    if (i < N_TOTAL) g_bins[i] = 0;
    if (i == 0) g_rcnt = 0;
}

// ---------------- prep: data -> g_Bv (permuted fp16) + g_dT (fp16 transpose) ----------------
__global__ __launch_bounds__(256)
void prep_data2(const float* __restrict__ data) {
    __shared__ float ts[32][33];
    const int tx = threadIdx.x, ty = threadIdx.y;
    const int k0 = blockIdx.x * 32, m0 = blockIdx.y * 32;
    #pragma unroll
    for (int i = 0; i < 4; i++)
        ts[ty + i * 8][tx] = data[(size_t)(m0 + ty + i * 8) * K_TOTAL + k0 + tx];
    __syncthreads();
    // dT: coalesced along m
    #pragma unroll
    for (int i = 0; i < 4; i++)
        g_dT[(size_t)(k0 + ty + i * 8) * M_TOTAL + m0 + tx] =
            __float2half(ts[tx][ty + i * 8]);
    // Bv: row m, permuted position p=tx -> source k
    {
        const int t = tx >> 3, rem = tx & 7, hh = rem >> 1, d = rem & 1;
        const int k = 8 * hh + 2 * t + d;
        #pragma unroll
        for (int i = 0; i < 4; i++)
            g_Bv[(size_t)(m0 + ty + i * 8) * K_TOTAL + k0 + tx] =
                __float2half(ts[ty + i * 8][k]);
    }
}

// ---------------- prep: W*mask -> 2:4 compressed + meta + residual ----------------
__global__ __launch_bounds__(128)
void prep_w(const float* __restrict__ w, const float* __restrict__ msk) {
    const int n  = blockIdx.x;
    const int kt = threadIdx.x;
    const float4* wp = reinterpret_cast<const float4*>(w   + (size_t)n * K_TOTAL + kt * 32);
    const float4* mp = reinterpret_cast<const float4*>(msk + (size_t)n * K_TOTAL + kt * 32);
    alignas(16) __half hh[16];
    uint32_t meta = 0;
    #pragma unroll
    for (int j = 0; j < 8; j++) {
        float4 wv = __ldg(wp + j);
        float4 mv4 = __ldg(mp + j);
        float pv[4] = {wv.x * mv4.x, wv.y * mv4.y, wv.z * mv4.z, wv.w * mv4.w};
        float mm[4] = {mv4.x, mv4.y, mv4.z, mv4.w};
        float v[4];
        int idx[4], cnt = 0;
        #pragma unroll
        for (int s = 0; s < 4; s++)
            if (mm[s] != 0.0f) { v[cnt] = pv[s]; idx[cnt] = s; cnt++; }
        int i0, i1; float v0, v1;
        if (cnt == 0)      { i0 = 0; i1 = 1; v0 = 0.f; v1 = 0.f; }
        else if (cnt == 1) {
            int p = idx[0];
            if (p == 3) { i0 = 2; i1 = 3; v0 = 0.f; v1 = v[0]; }
            else        { i0 = p; i1 = p + 1; v0 = v[0]; v1 = 0.f; }
        } else {
            i0 = idx[0]; i1 = idx[1]; v0 = v[0]; v1 = v[1];
            for (int s = 2; s < cnt; s++) {
                uint32_t pos = atomicAdd(&g_rcnt, 1u);
                if (pos < RES_CAP) {
                    g_rn[pos] = ((uint32_t)n << 12) | (uint32_t)(kt * 32 + j * 4 + idx[s]);
                    g_rv[pos] = v[s];
                }
            }
        }
        meta |= (uint32_t)(i0 | (i1 << 2)) << (4 * j);
        int c0 = 2 * j, c1 = 2 * j + 1;
        hh[((c0 >> 1) & 3) * 4 + (c0 >> 3) * 2 + (c0 & 1)] = __float2half(v0);
        hh[((c1 >> 1) & 3) * 4 + (c1 >> 3) * 2 + (c1 & 1)] = __float2half(v1);
    }
    uint4* dst = reinterpret_cast<uint4*>(g_Ac + (size_t)n * 2048 + kt * 16);
    dst[0] = reinterpret_cast<uint4*>(hh)[0];
    dst[1] = reinterpret_cast<uint4*>(hh)[1];
    g_meta[(size_t)n * KT_CNT + kt] = meta;
}

// ---------------- prep: assemble E registers ----------------
__global__ __launch_bounds__(256)
void prep_E() {
    int i = blockIdx.x * blockDim.x + threadIdx.x;       // 524288
    int nb = i >> 14, rem = i & 16383;
    int kt = rem >> 7, q = rem & 127;
    int p = q >> 1, h = q & 1;
    int r = (p >> 3) * 16 + (p & 7);
    int n0 = nb * 128 + r;
    uint32_t m0 = g_meta[(size_t)n0 * KT_CNT + kt];
    uint32_t m1 = g_meta[(size_t)(n0 + 8) * KT_CNT + kt];
    g_E[i] = ((m0 >> (16 * h)) & 0xFFFFu) | (((m1 >> (16 * h)) & 0xFFFFu) << 16);
}

// ---------------- residual sort by n ----------------
__global__ void rs_count() {
    uint32_t i = blockIdx.x * blockDim.x + threadIdx.x;
    if (i < g_rcnt && i < RES_CAP) atomicAdd(&g_bins[g_rn[i] >> 12], 1u);
}
__global__ __launch_bounds__(1024)
void rs_prefix() {
    __shared__ uint32_t ts[1024];
    int t = threadIdx.x;
    uint32_t loc[4], sum = 0;
    #pragma unroll
    for (int u = 0; u < 4; u++) { loc[u] = g_bins[t * 4 + u]; sum += loc[u]; }
    ts[t] = sum; __syncthreads();
    for (int off = 1; off < 1024; off <<= 1) {
        uint32_t v = (t >= off) ? ts[t - off] : 0; __syncthreads();
        ts[t] += v; __syncthreads();
    }
    uint32_t run = ts[t] - sum;
    #pragma unroll
    for (int u = 0; u < 4; u++) {
        g_start[t * 4 + u] = run; g_cursor[t * 4 + u] = run; run += loc[u];
    }
    if (t == 1023) g_start[N_TOTAL] = run;
}
__global__ void rs_scatter() {
    uint32_t i = blockIdx.x * blockDim.x + threadIdx.x;
    if (i < g_rcnt && i < RES_CAP) {
        uint32_t nk = g_rn[i];
        uint32_t pos = atomicAdd(&g_cursor[nk >> 12], 1u);
        g_srn[pos] = nk; g_srv[pos] = g_rv[i];
    }
}

// ---------------- sparse GEMM: outT = W_2:4 · data^T (R10 version, unchanged) ----------------
__device__ __forceinline__ void cp_async16(void* dst, const void* src) {
    unsigned sdst = (unsigned)__cvta_generic_to_shared(dst);
    asm volatile("cp.async.cg.shared.global [%0], [%1], 16;" :: "r"(sdst), "l"(src));
}

__device__ __forceinline__ void mma_sp(float* c,
                                       unsigned a0, unsigned a1, unsigned a2, unsigned a3,
                                       const uint4& b, unsigned e) {
    asm volatile(
        "mma.sp::ordered_metadata.sync.aligned.m16n8k32.row.col.f32.f16.f16.f32 "
        "{%0,%1,%2,%3}, {%4,%5,%6,%7}, {%8,%9,%10,%11}, {%0,%1,%2,%3}, %12, 0x0;"
        : "+f"(c[0]), "+f"(c[1]), "+f"(c[2]), "+f"(c[3])
        : "r"(a0), "r"(a1), "r"(a2), "r"(a3),
          "r"(b.x), "r"(b.y), "r"(b.z), "r"(b.w), "r"(e));
}

__global__ __launch_bounds__(256, 2)
void gemm_sp_kernel() {
    extern __shared__ char smem[];
    char* As = smem;                 // [STAGES][128][32B]
    char* Bs = smem + OFF_B;         // [STAGES][128][64B]
    uint32_t* Es = reinterpret_cast<uint32_t*>(smem + OFF_E);

    const int tid  = threadIdx.x;
    const int wid  = tid >> 5;
    const int lane = tid & 31;
    const int g    = lane >> 2;
    const int t4   = lane & 3;

    const int wn = (wid & 1) * 64;
    const int wm = (wid >> 1) * 32;

    const int Nb = blockIdx.y * 128;
    const int Mb = blockIdx.x * 128;

    float acc[4][4][4];
    #pragma unroll
    for (int i = 0; i < 4; i++)
        #pragma unroll
        for (int j = 0; j < 4; j++)
            #pragma unroll
            for (int r = 0; r < 4; r++) acc[i][j][r] = 0.0f;

    auto load_stage = [&](int kt) {
        const int buf = kt & (STAGES - 1);
        {   // A: 256 x 16B
            int row = tid >> 1, hb = tid & 1;
            cp_async16(As + buf * A_ST_BYTES + row * 32 + hb * 16,
                       g_Ac + (size_t)(Nb + row) * 2048 + kt * 16 + hb * 8);
        }
        #pragma unroll
        for (int it = 0; it < 2; it++) {   // B: 512 x 16B
            int idx = tid + it * 256;
            int row = idx >> 2, ch = idx & 3;
            cp_async16(Bs + buf * B_ST_BYTES + row * 64 + ch * 16,
                       g_Bv + (size_t)(Mb + row) * K_TOTAL + kt * 32 + ch * 8);
        }
        if (tid < 32)
            cp_async16(reinterpret_cast<char*>(Es) + buf * E_ST_BYTES + tid * 16,
                       g_E + ((size_t)blockIdx.y * KT_CNT + kt) * 128 + tid * 4);
        asm volatile("cp.async.commit_group;");
    };

    load_stage(0);
    load_stage(1);
    load_stage(2);

    for (int kt = 0; kt < KT_CNT; ++kt) {
        asm volatile("cp.async.wait_group 2;");
        __syncthreads();
        if (kt + 3 < KT_CNT) load_stage(kt + 3);
        else asm volatile("cp.async.commit_group;");

        const int buf = kt & (STAGES - 1);
        const char* Ab = As + buf * A_ST_BYTES;
        const char* Bb = Bs + buf * B_ST_BYTES;
        const uint32_t* Eb = Es + buf * 128;

        uint4 bQ[4];
        #pragma unroll
        for (int j = 0; j < 4; j++)
            bQ[j] = *reinterpret_cast<const uint4*>(Bb + (wm + j * 8 + g) * 64 + t4 * 16);

        #pragma unroll
        for (int i = 0; i < 4; i++) {
            int r = wn + i * 16 + g;
            uint2 ra = *reinterpret_cast<const uint2*>(Ab + r * 32 + t4 * 8);
            uint2 rb = *reinterpret_cast<const uint2*>(Ab + (r + 8) * 32 + t4 * 8);
            unsigned e = Eb[((wn >> 4) + i) * 16 + g * 2 + (t4 & 1)];
            #pragma unroll
            for (int j = 0; j < 4; j++)
                mma_sp(acc[i][j], ra.x, rb.x, ra.y, rb.y, bQ[j], e);
        }
    }

    // Epilogue: D(row = W-row n, col = data-row m) -> g_outT, float2 stores.
    #pragma unroll
    for (int i = 0; i < 4; i++) {
        int n0 = Nb + wn + i * 16 + g;
        #pragma unroll
        for (int j = 0; j < 4; j++) {
            int m0 = Mb + wm + j * 8 + 2 * t4;
            *reinterpret_cast<float2*>(g_outT + (size_t)n0 * M_TOTAL + m0) =
                make_float2(acc[i][j][0], acc[i][j][1]);
            *reinterpret_cast<float2*>(g_outT + (size_t)(n0 + 8) * M_TOTAL + m0) =
                make_float2(acc[i][j][2], acc[i][j][3]);
        }
    }
}

// ---------------- finalize: transpose + residual + bias in ONE pass ----------------
__global__ __launch_bounds__(256)
void finalize_res(float* __restrict__ out, const float* __restrict__ bias) {
    __shared__ float ts[32][33];       // ts[n_local][m_local]
    const int tx = threadIdx.x, ty = threadIdx.y;
    const int m0 = blockIdx.x * 32, n0 = blockIdx.y * 32;
    #pragma unroll
    for (int i = 0; i < 4; i++)
        ts[ty + i * 8][tx] = g_outT[(size_t)(n0 + ty + i * 8) * M_TOTAL + m0 + tx];
    __syncthreads();
    // residual: thread (tx,ty) exclusively owns ts[ty+i*8][tx]
    #pragma unroll
    for (int i = 0; i < 4; i++) {
        const int n = n0 + ty + i * 8;
        const uint32_t s0 = __ldg(&g_start[n]);
        const uint32_t e0 = __ldg(&g_start[n + 1]);
        if (s0 != e0) {
            float val = ts[ty + i * 8][tx];
            for (uint32_t q = s0; q < e0; q++) {
                int k = (int)(__ldg(&g_srn[q]) & 0xFFFu);
                val += __ldg(&g_srv[q]) *
                       __half2float(__ldg(&g_dT[(size_t)k * M_TOTAL + m0 + tx]));
            }
            ts[ty + i * 8][tx] = val;
        }
    }
    __syncthreads();
    const float b = __ldg(bias + n0 + tx);
    #pragma unroll
    for (int i = 0; i < 4; i++)
        out[(size_t)(m0 + ty + i * 8) * N_TOTAL + n0 + tx] = ts[tx][ty + i * 8] + b;
}

// ---------------- host ----------------
extern "C" void kernel_launch(void* const* d_in, const int* in_sizes, int n_in,
                              void* d_out, int out_size) {
    const float* data   = (const float*)d_in[0];
    const float* weight = (const float*)d_in[1];
    const float* w_mask = (const float*)d_in[2];
    const float* bias_p = (const float*)d_in[3];
    float* out = (float*)d_out;

    rs_zero<<<(N_TOTAL + 255) / 256, 256>>>();
    prep_data2<<<dim3(K_TOTAL / 32, M_TOTAL / 32), dim3(32, 8)>>>(data);
    prep_w<<<N_TOTAL, 128>>>(weight, w_mask);
    prep_E<<<(N_TOTAL / 128) * KT_CNT * 128 / 256, 256>>>();
    rs_count<<<RES_CAP / 256, 256>>>();
    rs_prefix<<<1, 1024>>>();
    rs_scatter<<<RES_CAP / 256, 256>>>();

    cudaFuncSetAttribute(gemm_sp_kernel,
                         cudaFuncAttributeMaxDynamicSharedMemorySize, SMEM_BYTES);
    gemm_sp_kernel<<<dim3(M_TOTAL / 128, N_TOTAL / 128), 256, SMEM_BYTES>>>();

    finalize_res<<<dim3(M_TOTAL / 32, N_TOTAL / 32), dim3(32, 8)>>>(out, bias_p);
}